// round 4
// baseline (speedup 1.0000x reference)
#include <cuda_runtime.h>

#define T_STEPS 50
#define BATCH   2048
#define D_IN    1156
#define H       128
#define OUT_N   10
#define KC      248          // Eigen kc: aarch64 default l1=16KB, mr=12, nr=4 -> 248

// Scratch: cur1[t][b][h] = (x[t,b,:] @ W1.T)[h]   (bias b1 added in scan)
__device__ float g_cur1[(size_t)T_STEPS * BATCH * H];  // 52.4 MB

// ---------------------------------------------------------------------------
// SGEMM emulating Eigen gebp accumulation:
//   C[i,j] = (((S0 + S1) + S2) + S3) + S4, panels of KC over k (ascending),
//   each S_p a single ascending-k fused-FMA chain from 0.
// 128x128 tile, BK=8, 256 threads, 8x8 micro-tile, dual accumulators.
// NOTE: KC=248 is a multiple of BK=8, so panel boundaries land on k0 steps.
// ---------------------------------------------------------------------------
__global__ __launch_bounds__(256, 1)
void gemm_xw1(const float* __restrict__ A, const float* __restrict__ W, int M, int K) {
    const int BK = 8;
    __shared__ float As[BK][128];
    __shared__ float Bs[BK][128];

    int tid = threadIdx.x;
    int block_m = blockIdx.x * 128;
    int tx = tid & 15;       // 0..15 -> 8 cols each
    int ty = tid >> 4;       // 0..15 -> 8 rows each

    float acc_t[8][8];       // total (panel-combined)
    float acc_p[8][8];       // current panel partial
#pragma unroll
    for (int i = 0; i < 8; i++)
#pragma unroll
        for (int j = 0; j < 8; j++) { acc_t[i][j] = 0.f; acc_p[i][j] = 0.f; }

    int lRow = tid >> 1;           // 0..127
    int lCol = (tid & 1) * 4;      // 0 or 4
    const float* Aptr = A + (size_t)(block_m + lRow) * K;
    const float* Wptr = W + (size_t)lRow * K;

    for (int k0 = 0; k0 < K; k0 += BK) {
        float4 av = make_float4(0.f, 0.f, 0.f, 0.f);
        float4 wv = make_float4(0.f, 0.f, 0.f, 0.f);
        if (k0 + lCol < K) {   // K % 4 == 0, full float4 valid when start in range
            av = *(const float4*)(Aptr + k0 + lCol);
            wv = *(const float4*)(Wptr + k0 + lCol);
        }
        As[lCol + 0][lRow] = av.x; As[lCol + 1][lRow] = av.y;
        As[lCol + 2][lRow] = av.z; As[lCol + 3][lRow] = av.w;
        Bs[lCol + 0][lRow] = wv.x; Bs[lCol + 1][lRow] = wv.y;
        Bs[lCol + 2][lRow] = wv.z; Bs[lCol + 3][lRow] = wv.w;
        __syncthreads();

#pragma unroll
        for (int kk = 0; kk < BK; kk++) {
            float ra[8], rb[8];
#pragma unroll
            for (int i = 0; i < 8; i++) ra[i] = As[kk][ty * 8 + i];
#pragma unroll
            for (int j = 0; j < 8; j++) rb[j] = Bs[kk][tx * 8 + j];
#pragma unroll
            for (int i = 0; i < 8; i++)
#pragma unroll
                for (int j = 0; j < 8; j++)
                    acc_p[i][j] = __fmaf_rn(ra[i], rb[j], acc_p[i][j]);
        }
        __syncthreads();

        // Panel boundary (KC multiple of BK) or end of K: fold partial into total.
        int knext = k0 + BK;
        if ((knext % KC) == 0 || knext >= K) {
#pragma unroll
            for (int i = 0; i < 8; i++)
#pragma unroll
                for (int j = 0; j < 8; j++) {
                    acc_t[i][j] = __fadd_rn(acc_t[i][j], acc_p[i][j]);
                    acc_p[i][j] = 0.f;
                }
        }
    }

#pragma unroll
    for (int i = 0; i < 8; i++) {
        float* crow = g_cur1 + (size_t)(block_m + ty * 8 + i) * H + tx * 8;
#pragma unroll
        for (int j = 0; j < 8; j += 4) {
            *(float4*)(crow + j) =
                make_float4(acc_t[i][j], acc_t[i][j + 1], acc_t[i][j + 2], acc_t[i][j + 3]);
        }
    }
}

// ---------------------------------------------------------------------------
// Persistent per-row LIF scan. One block = one batch row, 128 threads = H.
// Exact reference elementwise order:
//   mem = fsub(fadd(fadd(fadd(fmul(0.9,mem), fadd(gemm,b1)), rec), bV), reset)
//   rec dots: single accumulator, ascending index; spikes are 0/1 so
//   conditional fadd == mul+add == fma bit-exactly.
// ---------------------------------------------------------------------------
#define V1T_ELEMS (128 * 129)
#define SCAN_SMEM_BYTES ((V1T_ELEMS + OUT_N * 128 + OUT_N + 8) * 4)

__global__ __launch_bounds__(128)
void scan_kernel(const float* __restrict__ b1, const float* __restrict__ V1,
                 const float* __restrict__ bV1, const float* __restrict__ W2,
                 const float* __restrict__ b2, const float* __restrict__ V2,
                 const float* __restrict__ bV2, float* __restrict__ out) {
    extern __shared__ float smem[];
    float* V1t   = smem;                       // [j*129 + h] = V1[h][j]
    float* W2s   = smem + V1T_ELEMS;           // [o*128 + h]
    float* sspk2 = W2s + OUT_N * 128;          // [10]
    unsigned* s_mask = (unsigned*)(sspk2 + OUT_N); // [4]

    int b = blockIdx.x;
    int h = threadIdx.x;

    for (int idx = h; idx < 128 * 128; idx += 128) {
        int r = idx >> 7, c = idx & 127;
        V1t[c * 129 + r] = V1[idx];
    }
    for (int idx = h; idx < OUT_N * 128; idx += 128) W2s[idx] = W2[idx];

    float V2row[OUT_N];
    float b2h = 0.f, bV2h = 0.f, mem2 = 0.f;
    if (h < OUT_N) {
#pragma unroll
        for (int p = 0; p < OUT_N; p++) V2row[p] = V2[h * OUT_N + p];
        b2h = b2[h]; bV2h = bV2[h];
        sspk2[h] = 0.f;
    }
    if (h < 4) s_mask[h] = 0u;

    float b1h  = b1[h];
    float bV1h = bV1[h];
    float mem1 = 0.f;
    const float* curp = g_cur1 + (size_t)b * H + h;
    float* outp = out + (size_t)b * OUT_N;
    __syncthreads();

    for (int t = 0; t < T_STEPS; t++) {
        // layer 1 recurrent: single accumulator, ascending j
        float rec1 = 0.f;
#pragma unroll
        for (int w = 0; w < 4; w++) {
            unsigned m = s_mask[w];
            const float* col = V1t + (w * 32) * 129 + h;
            while (m) {
                int j = __ffs(m) - 1;
                m &= m - 1;
                rec1 = __fadd_rn(rec1, col[j * 129]);
            }
        }

        float gv    = curp[(size_t)t * BATCH * H];
        float cur1  = __fadd_rn(gv, b1h);
        float reset = (mem1 > 1.0f) ? 1.0f : 0.0f;
        float a     = __fmul_rn(0.9f, mem1);
        a = __fadd_rn(a, cur1);
        a = __fadd_rn(a, rec1);
        a = __fadd_rn(a, bV1h);
        mem1 = __fsub_rn(a, reset);
        float spk = (mem1 > 1.0f) ? 1.0f : 0.0f;

        unsigned bal = __ballot_sync(0xffffffffu, spk != 0.0f);
        __syncthreads();
        if ((h & 31) == 0) s_mask[h >> 5] = bal;
        __syncthreads();

        if (h < OUT_N) {
            float c2 = 0.f;
            const float* w2 = W2s + h * 128;
#pragma unroll
            for (int w = 0; w < 4; w++) {
                unsigned n = s_mask[w];
                const float* base = w2 + w * 32;
                while (n) {
                    int j = __ffs(n) - 1;
                    n &= n - 1;
                    c2 = __fadd_rn(c2, base[j]);
                }
            }
            float cur2 = __fadd_rn(c2, b2h);
            float rec2 = 0.f;
#pragma unroll
            for (int p = 0; p < OUT_N; p++) {
                if (sspk2[p] != 0.0f) rec2 = __fadd_rn(rec2, V2row[p]);
            }
            float reset2 = (mem2 > 1.0f) ? 1.0f : 0.0f;
            float u = __fmul_rn(0.9f, mem2);
            u = __fadd_rn(u, cur2);
            u = __fadd_rn(u, rec2);
            u = __fadd_rn(u, bV2h);
            mem2 = __fsub_rn(u, reset2);
            float s2 = (mem2 > 1.0f) ? 1.0f : 0.0f;
            outp[(size_t)t * BATCH * OUT_N + h] = s2;
            __syncwarp(0x3ffu);
            sspk2[h] = s2;
        }
        __syncthreads();
    }
}

extern "C" void kernel_launch(void* const* d_in, const int* in_sizes, int n_in,
                              void* d_out, int out_size) {
    const float* x   = (const float*)d_in[0];
    const float* W1  = (const float*)d_in[1];
    const float* b1  = (const float*)d_in[2];
    const float* V1  = (const float*)d_in[3];
    const float* bV1 = (const float*)d_in[4];
    const float* W2  = (const float*)d_in[5];
    const float* b2  = (const float*)d_in[6];
    const float* V2  = (const float*)d_in[7];
    const float* bV2 = (const float*)d_in[8];
    float* out = (float*)d_out;

    cudaFuncSetAttribute(scan_kernel, cudaFuncAttributeMaxDynamicSharedMemorySize,
                         SCAN_SMEM_BYTES);

    const int M = T_STEPS * BATCH;  // 102400
    gemm_xw1<<<M / 128, 256>>>(x, W1, M, D_IN);
    scan_kernel<<<BATCH, 128, SCAN_SMEM_BYTES>>>(b1, V1, bV1, W2, b2, V2, bV2, out);
}

// round 5
// speedup vs baseline: 1.2242x; 1.2242x over previous
#include <cuda_runtime.h>

#define T_STEPS 50
#define BATCH   2048
#define D_IN    1156
#define H       128
#define OUT_N   10
#define KC      248          // Eigen kc (aarch64 default l1=16KB) -- verified exact

// Scratch: cur1[t][b][h] = (x[t,b,:] @ W1.T)[h]   (bias b1 added in scan)
__device__ float g_cur1[(size_t)T_STEPS * BATCH * H];  // 52.4 MB

// ---------------------------------------------------------------------------
// SGEMM emulating Eigen gebp accumulation (bit-exact, verified):
//   C = ((((S0+S1)+S2)+S3)+S4, KC=248 panels, each an ascending-k FMA chain.
// 128x128 tile, BK=8, 256 threads, 8x8 micro-tile, DOUBLE-BUFFERED smem.
// ---------------------------------------------------------------------------
__global__ __launch_bounds__(256, 1)
void gemm_xw1(const float* __restrict__ A, const float* __restrict__ W, int M, int K) {
    const int BK = 8;
    __shared__ float As[2][BK][128];
    __shared__ float Bs[2][BK][128];

    int tid = threadIdx.x;
    int block_m = blockIdx.x * 128;
    int tx = tid & 15;
    int ty = tid >> 4;

    float acc_t[8][8];
    float acc_p[8][8];
#pragma unroll
    for (int i = 0; i < 8; i++)
#pragma unroll
        for (int j = 0; j < 8; j++) { acc_t[i][j] = 0.f; acc_p[i][j] = 0.f; }

    int lRow = tid >> 1;
    int lCol = (tid & 1) * 4;
    const float* Aptr = A + (size_t)(block_m + lRow) * K;
    const float* Wptr = W + (size_t)lRow * K;

    const int NIT = (K + BK - 1) / BK;   // 145

    float4 av, wv;
    // fetch tile 0
    {
        av = make_float4(0.f, 0.f, 0.f, 0.f);
        wv = make_float4(0.f, 0.f, 0.f, 0.f);
        if (lCol < K) {
            av = *(const float4*)(Aptr + lCol);
            wv = *(const float4*)(Wptr + lCol);
        }
        As[0][lCol + 0][lRow] = av.x; As[0][lCol + 1][lRow] = av.y;
        As[0][lCol + 2][lRow] = av.z; As[0][lCol + 3][lRow] = av.w;
        Bs[0][lCol + 0][lRow] = wv.x; Bs[0][lCol + 1][lRow] = wv.y;
        Bs[0][lCol + 2][lRow] = wv.z; Bs[0][lCol + 3][lRow] = wv.w;
    }
    __syncthreads();

    for (int it = 0; it < NIT; it++) {
        int cur = it & 1;
        int nxt = cur ^ 1;

        // prefetch next tile (global) while computing current
        if (it + 1 < NIT) {
            int k0 = (it + 1) * BK;
            av = make_float4(0.f, 0.f, 0.f, 0.f);
            wv = make_float4(0.f, 0.f, 0.f, 0.f);
            if (k0 + lCol < K) {
                av = *(const float4*)(Aptr + k0 + lCol);
                wv = *(const float4*)(Wptr + k0 + lCol);
            }
        }

#pragma unroll
        for (int kk = 0; kk < BK; kk++) {
            float ra[8], rb[8];
#pragma unroll
            for (int i = 0; i < 8; i++) ra[i] = As[cur][kk][ty * 8 + i];
#pragma unroll
            for (int j = 0; j < 8; j++) rb[j] = Bs[cur][kk][tx * 8 + j];
#pragma unroll
            for (int i = 0; i < 8; i++)
#pragma unroll
                for (int j = 0; j < 8; j++)
                    acc_p[i][j] = __fmaf_rn(ra[i], rb[j], acc_p[i][j]);
        }

        if (it + 1 < NIT) {
            As[nxt][lCol + 0][lRow] = av.x; As[nxt][lCol + 1][lRow] = av.y;
            As[nxt][lCol + 2][lRow] = av.z; As[nxt][lCol + 3][lRow] = av.w;
            Bs[nxt][lCol + 0][lRow] = wv.x; Bs[nxt][lCol + 1][lRow] = wv.y;
            Bs[nxt][lCol + 2][lRow] = wv.z; Bs[nxt][lCol + 3][lRow] = wv.w;
        }
        __syncthreads();

        // Eigen panel boundary: fold partial into total (KC multiple of BK)
        int knext = (it + 1) * BK;
        if ((knext % KC) == 0 || knext >= K) {
#pragma unroll
            for (int i = 0; i < 8; i++)
#pragma unroll
                for (int j = 0; j < 8; j++) {
                    acc_t[i][j] = __fadd_rn(acc_t[i][j], acc_p[i][j]);
                    acc_p[i][j] = 0.f;
                }
        }
    }

#pragma unroll
    for (int i = 0; i < 8; i++) {
        float* crow = g_cur1 + (size_t)(block_m + ty * 8 + i) * H + tx * 8;
#pragma unroll
        for (int j = 0; j < 8; j += 4) {
            *(float4*)(crow + j) =
                make_float4(acc_t[i][j], acc_t[i][j + 1], acc_t[i][j + 2], acc_t[i][j + 3]);
        }
    }
}

// ---------------------------------------------------------------------------
// Persistent LIF scan: 4 batch rows per block, 512 threads, shared V1t,
// double-buffered masks/spk2 -> ONE __syncthreads per timestep.
// Elementwise arithmetic identical to the verified R4 version.
// ---------------------------------------------------------------------------
#define ROWS_PB 4
#define SCAN_THREADS (ROWS_PB * H)          // 512
#define V1T_ELEMS (128 * 129)
#define W2_STRIDE 129
// floats: V1t + W2s + spk2[2][4][10] + masks(as float slots)[2][4][4]
#define SCAN_SMEM_FLOATS (V1T_ELEMS + OUT_N * W2_STRIDE + 2*ROWS_PB*OUT_N + 2*ROWS_PB*4)
#define SCAN_SMEM_BYTES (SCAN_SMEM_FLOATS * 4)

__global__ __launch_bounds__(SCAN_THREADS)
void scan_kernel(const float* __restrict__ b1, const float* __restrict__ V1,
                 const float* __restrict__ bV1, const float* __restrict__ W2,
                 const float* __restrict__ b2, const float* __restrict__ V2,
                 const float* __restrict__ bV2, float* __restrict__ out) {
    extern __shared__ float smem[];
    float* V1t   = smem;                                  // [j*129 + h] = V1[h][j]
    float* W2s   = smem + V1T_ELEMS;                      // [o*129 + j]
    float* sspk2 = W2s + OUT_N * W2_STRIDE;               // [buf][row][10]
    unsigned* s_mask = (unsigned*)(sspk2 + 2 * ROWS_PB * OUT_N); // [buf][row][4]

    int tid = threadIdx.x;
    int h   = tid & 127;
    int r   = tid >> 7;
    int b   = blockIdx.x * ROWS_PB + r;
    int wid = tid >> 5;              // warp id 0..15; row = wid>>2, word = wid&3

    for (int idx = tid; idx < 128 * 128; idx += SCAN_THREADS) {
        int rr = idx >> 7, cc = idx & 127;
        V1t[cc * 129 + rr] = V1[idx];
    }
    for (int idx = tid; idx < OUT_N * 128; idx += SCAN_THREADS) {
        int o = idx >> 7, j = idx & 127;
        W2s[o * W2_STRIDE + j] = W2[idx];
    }
    if (tid < 2 * ROWS_PB * OUT_N) sspk2[tid] = 0.f;
    if (tid < 2 * ROWS_PB * 4) s_mask[tid] = 0u;

    float V2row[OUT_N];
    float b2h = 0.f, bV2h = 0.f, mem2 = 0.f;
    if (h < OUT_N) {
#pragma unroll
        for (int p = 0; p < OUT_N; p++) V2row[p] = V2[h * OUT_N + p];
        b2h = b2[h]; bV2h = bV2[h];
    }

    float b1h  = b1[h];
    float bV1h = bV1[h];
    float mem1 = 0.f;
    const float* curp = g_cur1 + (size_t)b * H + h;
    float* outbase = out + (size_t)b * OUT_N + h;
    __syncthreads();

    for (int t = 0; t < T_STEPS; t++) {
        int pw = t & 1;          // buffer for step t's masks/spk2
        int pr = pw ^ 1;         // buffer holding step t-1's

        // ---- layer 1: rec term (single accumulator, ascending j) ----
        float rec1 = 0.f;
#pragma unroll
        for (int w = 0; w < 4; w++) {
            unsigned m = s_mask[(pr * ROWS_PB + r) * 4 + w];
            const float* col = V1t + (w * 32) * 129 + h;
            while (m) {
                int j = __ffs(m) - 1;
                m &= m - 1;
                rec1 = __fadd_rn(rec1, col[j * 129]);
            }
        }

        float gv    = curp[(size_t)t * BATCH * H];
        float cur1  = __fadd_rn(gv, b1h);
        float reset = (mem1 > 1.0f) ? 1.0f : 0.0f;
        float a     = __fmul_rn(0.9f, mem1);
        a = __fadd_rn(a, cur1);
        a = __fadd_rn(a, rec1);
        a = __fadd_rn(a, bV1h);
        mem1 = __fsub_rn(a, reset);
        float spk = (mem1 > 1.0f) ? 1.0f : 0.0f;

        unsigned bal = __ballot_sync(0xffffffffu, spk != 0.0f);
        if ((tid & 31) == 0) s_mask[(pw * ROWS_PB + (wid >> 2)) * 4 + (wid & 3)] = bal;
        __syncthreads();                 // masks(t) visible; spk2(t-1) reads done

        // ---- layer 2 (lanes h<10 of warp0 of each row); overlaps next layer1 ----
        if (h < OUT_N) {
            float c2 = 0.f;
            const float* w2 = W2s + h * W2_STRIDE;
#pragma unroll
            for (int w = 0; w < 4; w++) {
                unsigned n = s_mask[(pw * ROWS_PB + r) * 4 + w];
                const float* base = w2 + w * 32;
                while (n) {
                    int j = __ffs(n) - 1;
                    n &= n - 1;
                    c2 = __fadd_rn(c2, base[j]);
                }
            }
            float cur2 = __fadd_rn(c2, b2h);
            float rec2 = 0.f;
            const float* sp_prev = sspk2 + (pr * ROWS_PB + r) * OUT_N;
#pragma unroll
            for (int p = 0; p < OUT_N; p++) {
                if (sp_prev[p] != 0.0f) rec2 = __fadd_rn(rec2, V2row[p]);
            }
            float reset2 = (mem2 > 1.0f) ? 1.0f : 0.0f;
            float u = __fmul_rn(0.9f, mem2);
            u = __fadd_rn(u, cur2);
            u = __fadd_rn(u, rec2);
            u = __fadd_rn(u, bV2h);
            mem2 = __fsub_rn(u, reset2);
            float s2 = (mem2 > 1.0f) ? 1.0f : 0.0f;
            outbase[(size_t)t * BATCH * OUT_N] = s2;
            sspk2[(pw * ROWS_PB + r) * OUT_N + h] = s2;
        }
        // next iteration's __syncthreads orders spk2(t) writes vs reads at t+1
    }
}

extern "C" void kernel_launch(void* const* d_in, const int* in_sizes, int n_in,
                              void* d_out, int out_size) {
    const float* x   = (const float*)d_in[0];
    const float* W1  = (const float*)d_in[1];
    const float* b1  = (const float*)d_in[2];
    const float* V1  = (const float*)d_in[3];
    const float* bV1 = (const float*)d_in[4];
    const float* W2  = (const float*)d_in[5];
    const float* b2  = (const float*)d_in[6];
    const float* V2  = (const float*)d_in[7];
    const float* bV2 = (const float*)d_in[8];
    float* out = (float*)d_out;

    cudaFuncSetAttribute(scan_kernel, cudaFuncAttributeMaxDynamicSharedMemorySize,
                         SCAN_SMEM_BYTES);

    const int M = T_STEPS * BATCH;  // 102400
    gemm_xw1<<<M / 128, 256>>>(x, W1, M, D_IN);
    scan_kernel<<<BATCH / ROWS_PB, SCAN_THREADS, SCAN_SMEM_BYTES>>>(
        b1, V1, bV1, W2, b2, V2, bV2, out);
}

// round 6
// speedup vs baseline: 1.8014x; 1.4715x over previous
#include <cuda_runtime.h>

#define T_STEPS 50
#define BATCH   2048
#define D_IN    1156
#define H       128
#define OUT_N   10
#define KC      248          // Eigen kc (aarch64 default l1=16KB) -- verified exact

// Scratch: cur1[t][b][h] = (x[t,b,:] @ W1.T)[h]   (bias b1 added in scan)
__device__ float g_cur1[(size_t)T_STEPS * BATCH * H];  // 52.4 MB

// ---------------------------------------------------------------------------
// SGEMM emulating Eigen gebp accumulation (bit-exact, verified R4):
//   C = ((((S0+S1)+S2)+S3)+S4, KC=248 panels, each an ascending-k FMA chain.
// Panel fold done in GMEM: panel 0 stores, panels 1..4 do load+__fadd_rn+store
// (left-to-right fold, bit-identical to in-register fold).
// 128x128 tile, BK=8, 256 threads, 8x8 micro-tile, double-buffered smem,
// SINGLE accumulator set -> ~110 regs -> 2 blocks/SM.
// ---------------------------------------------------------------------------
__global__ __launch_bounds__(256, 2)
void gemm_xw1(const float* __restrict__ A, const float* __restrict__ W, int M, int K) {
    const int BK = 8;
    __shared__ float As[2][BK][128];
    __shared__ float Bs[2][BK][128];

    int tid = threadIdx.x;
    int block_m = blockIdx.x * 128;
    int tx = tid & 15;
    int ty = tid >> 4;

    float acc[8][8];
#pragma unroll
    for (int i = 0; i < 8; i++)
#pragma unroll
        for (int j = 0; j < 8; j++) acc[i][j] = 0.f;

    int lRow = tid >> 1;
    int lCol = (tid & 1) * 4;
    const float* Aptr = A + (size_t)(block_m + lRow) * K;
    const float* Wptr = W + (size_t)lRow * K;

    const int NIT = (K + BK - 1) / BK;   // 145

    float4 av, wv;
    {   // fetch tile 0
        av = make_float4(0.f, 0.f, 0.f, 0.f);
        wv = make_float4(0.f, 0.f, 0.f, 0.f);
        if (lCol < K) {
            av = *(const float4*)(Aptr + lCol);
            wv = *(const float4*)(Wptr + lCol);
        }
        As[0][lCol + 0][lRow] = av.x; As[0][lCol + 1][lRow] = av.y;
        As[0][lCol + 2][lRow] = av.z; As[0][lCol + 3][lRow] = av.w;
        Bs[0][lCol + 0][lRow] = wv.x; Bs[0][lCol + 1][lRow] = wv.y;
        Bs[0][lCol + 2][lRow] = wv.z; Bs[0][lCol + 3][lRow] = wv.w;
    }
    __syncthreads();

    int panel_done = 0;
    float* cbase = g_cur1 + (size_t)(block_m + ty * 8) * H + tx * 8;

    for (int it = 0; it < NIT; it++) {
        int cur = it & 1;
        int nxt = cur ^ 1;

        if (it + 1 < NIT) {   // prefetch next tile while computing current
            int k0 = (it + 1) * BK;
            av = make_float4(0.f, 0.f, 0.f, 0.f);
            wv = make_float4(0.f, 0.f, 0.f, 0.f);
            if (k0 + lCol < K) {   // zero-pad tail; zeros are exact FMA no-ops
                av = *(const float4*)(Aptr + k0 + lCol);
                wv = *(const float4*)(Wptr + k0 + lCol);
            }
        }

#pragma unroll
        for (int kk = 0; kk < BK; kk++) {
            float ra[8], rb[8];
#pragma unroll
            for (int i = 0; i < 8; i++) ra[i] = As[cur][kk][ty * 8 + i];
#pragma unroll
            for (int j = 0; j < 8; j++) rb[j] = Bs[cur][kk][tx * 8 + j];
#pragma unroll
            for (int i = 0; i < 8; i++)
#pragma unroll
                for (int j = 0; j < 8; j++)
                    acc[i][j] = __fmaf_rn(ra[i], rb[j], acc[i][j]);
        }

        if (it + 1 < NIT) {
            As[nxt][lCol + 0][lRow] = av.x; As[nxt][lCol + 1][lRow] = av.y;
            As[nxt][lCol + 2][lRow] = av.z; As[nxt][lCol + 3][lRow] = av.w;
            Bs[nxt][lCol + 0][lRow] = wv.x; Bs[nxt][lCol + 1][lRow] = wv.y;
            Bs[nxt][lCol + 2][lRow] = wv.z; Bs[nxt][lCol + 3][lRow] = wv.w;
        }
        __syncthreads();

        // Eigen panel boundary: fold partial into C (gmem), left-to-right.
        int knext = (it + 1) * BK;
        if ((knext % KC) == 0 || knext >= K) {
            if (panel_done == 0) {
#pragma unroll
                for (int i = 0; i < 8; i++) {
                    float* crow = cbase + (size_t)i * H;
#pragma unroll
                    for (int j = 0; j < 8; j += 4)
                        *(float4*)(crow + j) = make_float4(acc[i][j], acc[i][j+1],
                                                           acc[i][j+2], acc[i][j+3]);
                }
            } else {
#pragma unroll
                for (int i = 0; i < 8; i++) {
                    float* crow = cbase + (size_t)i * H;
#pragma unroll
                    for (int j = 0; j < 8; j += 4) {
                        float4 c = *(float4*)(crow + j);
                        c.x = __fadd_rn(c.x, acc[i][j    ]);
                        c.y = __fadd_rn(c.y, acc[i][j + 1]);
                        c.z = __fadd_rn(c.z, acc[i][j + 2]);
                        c.w = __fadd_rn(c.w, acc[i][j + 3]);
                        *(float4*)(crow + j) = c;
                    }
                }
            }
            panel_done++;
#pragma unroll
            for (int i = 0; i < 8; i++)
#pragma unroll
                for (int j = 0; j < 8; j++) acc[i][j] = 0.f;
        }
    }
}

// ---------------------------------------------------------------------------
// Persistent LIF scan: 8 batch rows per block, 1024 threads, shared V1t,
// double-buffered masks/spk2 -> one __syncthreads per timestep.
// grid=256, 2 blocks/SM -> single wave. Arithmetic identical to verified R4.
// ---------------------------------------------------------------------------
#define ROWS_PB 8
#define SCAN_THREADS (ROWS_PB * H)          // 1024
#define V1T_ELEMS (128 * 129)
#define W2_STRIDE 129
#define SCAN_SMEM_FLOATS (V1T_ELEMS + OUT_N * W2_STRIDE + 2*ROWS_PB*OUT_N + 2*ROWS_PB*4)
#define SCAN_SMEM_BYTES (SCAN_SMEM_FLOATS * 4)

__global__ __launch_bounds__(SCAN_THREADS, 2)
void scan_kernel(const float* __restrict__ b1, const float* __restrict__ V1,
                 const float* __restrict__ bV1, const float* __restrict__ W2,
                 const float* __restrict__ b2, const float* __restrict__ V2,
                 const float* __restrict__ bV2, float* __restrict__ out) {
    extern __shared__ float smem[];
    float* V1t   = smem;                                  // [j*129 + h] = V1[h][j]
    float* W2s   = smem + V1T_ELEMS;                      // [o*129 + j]
    float* sspk2 = W2s + OUT_N * W2_STRIDE;               // [buf][row][10]
    unsigned* s_mask = (unsigned*)(sspk2 + 2 * ROWS_PB * OUT_N); // [buf][row][4]

    int tid = threadIdx.x;
    int h   = tid & 127;
    int r   = tid >> 7;
    int b   = blockIdx.x * ROWS_PB + r;
    int wid = tid >> 5;              // warp id; row = wid>>2, word = wid&3

    for (int idx = tid; idx < 128 * 128; idx += SCAN_THREADS) {
        int rr = idx >> 7, cc = idx & 127;
        V1t[cc * 129 + rr] = V1[idx];
    }
    for (int idx = tid; idx < OUT_N * 128; idx += SCAN_THREADS) {
        int o = idx >> 7, j = idx & 127;
        W2s[o * W2_STRIDE + j] = W2[idx];
    }
    if (tid < 2 * ROWS_PB * OUT_N) sspk2[tid] = 0.f;
    if (tid < 2 * ROWS_PB * 4) s_mask[tid] = 0u;

    float V2row[OUT_N];
    float b2h = 0.f, bV2h = 0.f, mem2 = 0.f;
    if (h < OUT_N) {
#pragma unroll
        for (int p = 0; p < OUT_N; p++) V2row[p] = V2[h * OUT_N + p];
        b2h = b2[h]; bV2h = bV2[h];
    }

    float b1h  = b1[h];
    float bV1h = bV1[h];
    float mem1 = 0.f;
    const float* curp = g_cur1 + (size_t)b * H + h;
    float* outbase = out + (size_t)b * OUT_N + h;
    __syncthreads();

    for (int t = 0; t < T_STEPS; t++) {
        int pw = t & 1;
        int pr = pw ^ 1;

        // ---- layer 1: rec term (single accumulator, ascending j) ----
        float rec1 = 0.f;
#pragma unroll
        for (int w = 0; w < 4; w++) {
            unsigned m = s_mask[(pr * ROWS_PB + r) * 4 + w];
            const float* col = V1t + (w * 32) * 129 + h;
            while (m) {
                int j = __ffs(m) - 1;
                m &= m - 1;
                rec1 = __fadd_rn(rec1, col[j * 129]);
            }
        }

        float gv    = curp[(size_t)t * BATCH * H];
        float cur1  = __fadd_rn(gv, b1h);
        float reset = (mem1 > 1.0f) ? 1.0f : 0.0f;
        float a     = __fmul_rn(0.9f, mem1);
        a = __fadd_rn(a, cur1);
        a = __fadd_rn(a, rec1);
        a = __fadd_rn(a, bV1h);
        mem1 = __fsub_rn(a, reset);
        float spk = (mem1 > 1.0f) ? 1.0f : 0.0f;

        unsigned bal = __ballot_sync(0xffffffffu, spk != 0.0f);
        if ((tid & 31) == 0) s_mask[(pw * ROWS_PB + (wid >> 2)) * 4 + (wid & 3)] = bal;
        __syncthreads();                 // masks(t) visible; spk2(t-1) reads done

        // ---- layer 2 (lanes h<10 of first warp of each row) ----
        if (h < OUT_N) {
            float c2 = 0.f;
            const float* w2 = W2s + h * W2_STRIDE;
#pragma unroll
            for (int w = 0; w < 4; w++) {
                unsigned n = s_mask[(pw * ROWS_PB + r) * 4 + w];
                const float* base = w2 + w * 32;
                while (n) {
                    int j = __ffs(n) - 1;
                    n &= n - 1;
                    c2 = __fadd_rn(c2, base[j]);
                }
            }
            float cur2 = __fadd_rn(c2, b2h);
            float rec2 = 0.f;
            const float* sp_prev = sspk2 + (pr * ROWS_PB + r) * OUT_N;
#pragma unroll
            for (int p = 0; p < OUT_N; p++) {
                if (sp_prev[p] != 0.0f) rec2 = __fadd_rn(rec2, V2row[p]);
            }
            float reset2 = (mem2 > 1.0f) ? 1.0f : 0.0f;
            float u = __fmul_rn(0.9f, mem2);
            u = __fadd_rn(u, cur2);
            u = __fadd_rn(u, rec2);
            u = __fadd_rn(u, bV2h);
            mem2 = __fsub_rn(u, reset2);
            float s2 = (mem2 > 1.0f) ? 1.0f : 0.0f;
            outbase[(size_t)t * BATCH * OUT_N] = s2;
            sspk2[(pw * ROWS_PB + r) * OUT_N + h] = s2;
        }
        // next iteration's __syncthreads orders spk2(t) writes vs reads at t+1
    }
}

extern "C" void kernel_launch(void* const* d_in, const int* in_sizes, int n_in,
                              void* d_out, int out_size) {
    const float* x   = (const float*)d_in[0];
    const float* W1  = (const float*)d_in[1];
    const float* b1  = (const float*)d_in[2];
    const float* V1  = (const float*)d_in[3];
    const float* bV1 = (const float*)d_in[4];
    const float* W2  = (const float*)d_in[5];
    const float* b2  = (const float*)d_in[6];
    const float* V2  = (const float*)d_in[7];
    const float* bV2 = (const float*)d_in[8];
    float* out = (float*)d_out;

    cudaFuncSetAttribute(scan_kernel, cudaFuncAttributeMaxDynamicSharedMemorySize,
                         SCAN_SMEM_BYTES);

    const int M = T_STEPS * BATCH;  // 102400
    gemm_xw1<<<M / 128, 256>>>(x, W1, M, D_IN);
    scan_kernel<<<BATCH / ROWS_PB, SCAN_THREADS, SCAN_SMEM_BYTES>>>(
        b1, V1, bV1, W2, b2, V2, bV2, out);
}